// round 7
// baseline (speedup 1.0000x reference)
#include <cuda_runtime.h>

// AdderNet: out[n,h,w,f] = sum_{dh,dw,c} |Xpad[n,h+dh-1,w+dw-1,c] - F[f,dh,dw,c]|
// X [8,32,32,32] f32 NHWC, F [64,3,3,32] f32, out [8,32,32,64] f32.
//
// R7: filters read via LDG (L1D-resident, ~18KB/quarter); smem holds only X
// (13KB) -> 8 CTA/SM (reg-capped), 32 warps/SM. Issue-port-bound core:
// FFMA2 + 2xLOP3 + FADD2 per packed channel-pair.
// Grid (256 nh, 4 fq), block 128 = wq(16) x fg(8); thread 2px x 2f.

#define XS_F4 (3 * 8 * 34)          // 816 float4, swizzle s = r*17+q, wp = 2q+r
#define SMEM_BYTES (XS_F4 * 16)     // 13,056 B

typedef unsigned long long u64;

__device__ __forceinline__ u64 ffma2(u64 a, u64 b, u64 c) {
    u64 r;
    asm("fma.rn.f32x2 %0, %1, %2, %3;" : "=l"(r) : "l"(a), "l"(b), "l"(c));
    return r;
}
__device__ __forceinline__ u64 fadd2(u64 a, u64 b) {
    u64 r;
    asm("add.rn.f32x2 %0, %1, %2;" : "=l"(r) : "l"(a), "l"(b));
    return r;
}

__global__ __launch_bounds__(128, 8)
void adder_layer_kernel(const float* __restrict__ X,
                        const float* __restrict__ Fw,
                        float* __restrict__ out) {
    extern __shared__ __align__(16) float4 smem4[];
    float4* Xs4 = smem4;              // [(dh*8 + c4)*34 + s]

    const int tid = threadIdx.x;
    const int nh = blockIdx.x;        // n*32 + h
    const int fbase = blockIdx.y * 16;
    const int n = nh >> 5;
    const int h = nh & 31;

    // ---- X fill: 3 rows, swizzled s = r*17 + q (wp = 2q + r), zero-padded ----
    const float4* Xg4 = reinterpret_cast<const float4*>(X);
    for (int i = tid; i < XS_F4; i += 128) {
        int c4 = i & 7;
        int t = i >> 3;
        int s = t % 34;
        int dh = t / 34;
        int q = s % 17, r = s / 17;
        int wp = 2 * q + r;
        int row = h - 1 + dh;
        int w = wp - 1;
        float4 v = make_float4(0.f, 0.f, 0.f, 0.f);
        if (row >= 0 && row < 32 && w >= 0 && w < 32)
            v = Xg4[(((n * 32) + row) * 32 + w) * 8 + c4];
        Xs4[(dh * 8 + c4) * 34 + s] = v;
    }
    __syncthreads();

    const int wq = tid & 15;          // pixels w = 2wq, 2wq+1
    const int fg = tid >> 4;          // 0..7 -> filters fbase+2fg, fbase+2fg+1

    const u64 NEG1 = 0xBF800000BF800000ULL;
    const u64 ABSM = 0x7FFFFFFF7FFFFFFFULL;

    u64 acc[2][2] = {{0ull, 0ull}, {0ull, 0ull}};   // [filter][pixel]

    const ulonglong2* Xu = reinterpret_cast<const ulonglong2*>(Xs4);
    // Filters direct from global (L1-cached): float4 index f*72 + dh*24 + dw*8 + c4
    const ulonglong2* __restrict__ Fg = reinterpret_cast<const ulonglong2*>(Fw);
    const ulonglong2* __restrict__ Fb0 = Fg + (fbase + 2 * fg) * 72;
    const ulonglong2* __restrict__ Fb1 = Fb0 + 72;

    // x slots for wp = 2wq + k: {wq, 17+wq, wq+1, 18+wq}
    ulonglong2 cur0, cur1, cur2, cur3;
    {
        const ulonglong2* xr = Xu + wq;
        cur0 = xr[0]; cur1 = xr[17]; cur2 = xr[1]; cur3 = xr[18];
    }

    #pragma unroll 4
    for (int kk = 0; kk < 24; kk++) {
        const int dh = kk >> 3;
        const int c4 = kk & 7;
        const int foff = dh * 24 + c4;

        // filter taps via LDG (L1-resident after first touch)
        ulonglong2 t00 = __ldg(Fb0 + foff);
        ulonglong2 t01 = __ldg(Fb0 + foff + 8);
        ulonglong2 t02 = __ldg(Fb0 + foff + 16);
        ulonglong2 t10 = __ldg(Fb1 + foff);
        ulonglong2 t11 = __ldg(Fb1 + foff + 8);
        ulonglong2 t12 = __ldg(Fb1 + foff + 16);

        // prefetch next iteration's x from smem
        ulonglong2 nxt0, nxt1, nxt2, nxt3;
        {
            int kn = (kk < 23) ? kk + 1 : 23;
            const ulonglong2* xr = Xu + kn * 34 + wq;
            nxt0 = xr[0]; nxt1 = xr[17]; nxt2 = xr[1]; nxt3 = xr[18];
        }

        acc[0][0] = fadd2(acc[0][0], ffma2(t00.x, NEG1, cur0.x) & ABSM);
        acc[0][0] = fadd2(acc[0][0], ffma2(t00.y, NEG1, cur0.y) & ABSM);
        acc[0][0] = fadd2(acc[0][0], ffma2(t01.x, NEG1, cur1.x) & ABSM);
        acc[0][0] = fadd2(acc[0][0], ffma2(t01.y, NEG1, cur1.y) & ABSM);
        acc[0][0] = fadd2(acc[0][0], ffma2(t02.x, NEG1, cur2.x) & ABSM);
        acc[0][0] = fadd2(acc[0][0], ffma2(t02.y, NEG1, cur2.y) & ABSM);

        acc[0][1] = fadd2(acc[0][1], ffma2(t00.x, NEG1, cur1.x) & ABSM);
        acc[0][1] = fadd2(acc[0][1], ffma2(t00.y, NEG1, cur1.y) & ABSM);
        acc[0][1] = fadd2(acc[0][1], ffma2(t01.x, NEG1, cur2.x) & ABSM);
        acc[0][1] = fadd2(acc[0][1], ffma2(t01.y, NEG1, cur2.y) & ABSM);
        acc[0][1] = fadd2(acc[0][1], ffma2(t02.x, NEG1, cur3.x) & ABSM);
        acc[0][1] = fadd2(acc[0][1], ffma2(t02.y, NEG1, cur3.y) & ABSM);

        acc[1][0] = fadd2(acc[1][0], ffma2(t10.x, NEG1, cur0.x) & ABSM);
        acc[1][0] = fadd2(acc[1][0], ffma2(t10.y, NEG1, cur0.y) & ABSM);
        acc[1][0] = fadd2(acc[1][0], ffma2(t11.x, NEG1, cur1.x) & ABSM);
        acc[1][0] = fadd2(acc[1][0], ffma2(t11.y, NEG1, cur1.y) & ABSM);
        acc[1][0] = fadd2(acc[1][0], ffma2(t12.x, NEG1, cur2.x) & ABSM);
        acc[1][0] = fadd2(acc[1][0], ffma2(t12.y, NEG1, cur2.y) & ABSM);

        acc[1][1] = fadd2(acc[1][1], ffma2(t10.x, NEG1, cur1.x) & ABSM);
        acc[1][1] = fadd2(acc[1][1], ffma2(t10.y, NEG1, cur1.y) & ABSM);
        acc[1][1] = fadd2(acc[1][1], ffma2(t11.x, NEG1, cur2.x) & ABSM);
        acc[1][1] = fadd2(acc[1][1], ffma2(t11.y, NEG1, cur2.y) & ABSM);
        acc[1][1] = fadd2(acc[1][1], ffma2(t12.x, NEG1, cur3.x) & ABSM);
        acc[1][1] = fadd2(acc[1][1], ffma2(t12.y, NEG1, cur3.y) & ABSM);

        cur0 = nxt0; cur1 = nxt1; cur2 = nxt2; cur3 = nxt3;
    }

    // ---- Epilogue: horizontal add of packed lanes, float2 store per pixel ----
    #pragma unroll
    for (int p = 0; p < 2; p++) {
        u64 a0 = acc[0][p], a1 = acc[1][p];
        float r0 = __uint_as_float((unsigned)a0) + __uint_as_float((unsigned)(a0 >> 32));
        float r1 = __uint_as_float((unsigned)a1) + __uint_as_float((unsigned)(a1 >> 32));
        *reinterpret_cast<float2*>(
            out + ((nh * 32) + 2 * wq + p) * 64 + fbase + 2 * fg) = make_float2(r0, r1);
    }
}

extern "C" void kernel_launch(void* const* d_in, const int* in_sizes, int n_in,
                              void* d_out, int out_size) {
    const float* X = (const float*)d_in[0];
    const float* Fw = (const float*)d_in[1];
    float* out = (float*)d_out;

    cudaFuncSetAttribute(adder_layer_kernel,
                         cudaFuncAttributeMaxDynamicSharedMemorySize, SMEM_BYTES);
    dim3 grid(256, 4);
    adder_layer_kernel<<<grid, 128, SMEM_BYTES>>>(X, Fw, out);
}